// round 13
// baseline (speedup 1.0000x reference)
#include <cuda_runtime.h>
#include <cstdint>
#include <math.h>

// Problem constants
#define BB 8
#define CC 512
#define NN 4096   // H*W
#define DD 32     // C / R

// Scratch (allocation-free rule: __device__ globals)
__device__ float g_qk[BB * 2 * DD * NN];               // [b][64][n]: rows 0-31=q, 32-63=k
__device__ float g_v [(size_t)BB * CC * NN];           // v[b][c][m]  (raw fp32)
__device__ float g_xT[(size_t)BB * CC * NN];           // xT[b][n][c] (tf32-rounded)
__device__ float g_P [(size_t)BB * NN * NN];           // P'[b][n][m] (tf32-rounded)
__device__ float g_Wv[CC * CC];                        // Wv tf32-rounded
__device__ float g_Wqk[2 * DD * CC];                   // concat [Wq; Wk]
__device__ float g_rsp[BB * 32 * NN];                  // partial column sums
__device__ float g_irs[BB * NN];                       // 1 / rowsum[b][m]

// ============================================================================
// helpers
// ============================================================================
__device__ __forceinline__ uint32_t smem_u32(const void* p) {
    uint32_t a;
    asm("{ .reg .u64 t; cvta.to.shared.u64 t, %1; cvt.u32.u64 %0, t; }"
        : "=r"(a) : "l"(p));
    return a;
}
__device__ __forceinline__ void cpa16(uint32_t dst, const void* src) {
    asm volatile("cp.async.cg.shared.global [%0], [%1], 16;"
                 :: "r"(dst), "l"(src));
}
__device__ __forceinline__ float rntf32(float f) {
    uint32_t u;
    asm("cvt.rna.tf32.f32 %0, %1;" : "=r"(u) : "f"(f));
    return __uint_as_float(u);
}
__device__ __forceinline__ void mma_tf32(float c[4],
                                         uint32_t a0, uint32_t a1, uint32_t a2, uint32_t a3,
                                         uint32_t b0, uint32_t b1) {
    asm volatile(
        "mma.sync.aligned.m16n8k8.row.col.f32.tf32.tf32.f32 "
        "{%0,%1,%2,%3}, {%4,%5,%6,%7}, {%8,%9}, {%0,%1,%2,%3};"
        : "+f"(c[0]), "+f"(c[1]), "+f"(c[2]), "+f"(c[3])
        : "r"(a0), "r"(a1), "r"(a2), "r"(a3), "r"(b0), "r"(b1));
}

// ============================================================================
// tf32 mma.sync GEMM: C[m][n] = sum_k A[m][k] * B[n][k]
// Block tile 128(M) x 128(N) x 32(K); 8 warps, each 64x32.
// 3-stage pipeline, cross-tile fragment ping-pong.
// SCALE_A: A-tile goes LDG (+ *inv_rs[k] + rntf32) + STS, software-pipelined
//          (LDG for tile t+2 at ks=0, STS at ks=3); B stays cp.async.
//          Otherwise A+B both cp.async (inputs pre-rounded).
// ============================================================================
#define MG_STRIDE 36
#define MG_TSZ (128 * MG_STRIDE)              // floats, per operand per stage
#define MG_STAGE_FLOATS (2 * MG_TSZ)
#define MG_STAGES 3
#define MG_SMEM_BYTES (MG_STAGES * MG_STAGE_FLOATS * 4)   // 110592

template <bool SCALE_A>
__global__ void __launch_bounds__(256)
mma_gemm(const float* __restrict__ A, const float* __restrict__ B,
         const float* __restrict__ irs_g,
         float* __restrict__ C, int K,
         long long sA, long long sB, long long sC, int ldc)
{
    extern __shared__ float sm[];
    const uint32_t sb = smem_u32(sm);

    const int tid = threadIdx.x;
    const int lane = tid & 31;
    const int wid = tid >> 5;
    const int g = lane >> 2;
    const int tg = lane & 3;
    const int wm = wid & 1;        // 2 warps along M (64 each)
    const int wn = wid >> 1;       // 4 warps along N (32 each)

    const long long bz = blockIdx.z;
    const int bm = blockIdx.y * 128;
    const int bn = blockIdx.x * 128;
    const float* Ag = A + bz * sA + (size_t)bm * K;
    const float* Bg = B + bz * sB + (size_t)bn * K;
    const float* irs = SCALE_A ? (irs_g + bz * NN) : nullptr;

    float acc[4][4][4];
#pragma unroll
    for (int mf = 0; mf < 4; mf++)
#pragma unroll
        for (int nf = 0; nf < 4; nf++)
#pragma unroll
            for (int i = 0; i < 4; i++) acc[mf][nf][i] = 0.f;

    const int row = tid >> 3;      // 0..31
    const int k4  = tid & 7;       // 0..7

    // ---- B tile via cp.async (one commit group per tile) ----
    auto loadB = [&](int t) {
        const int s = t % MG_STAGES;
        const int k0 = t * 32;
        const uint32_t bbase = sb + (uint32_t)(s * MG_STAGE_FLOATS + MG_TSZ) * 4;
#pragma unroll
        for (int it = 0; it < 4; it++) {
            int r = it * 32 + row;
            cpa16(bbase + (uint32_t)(r * MG_STRIDE + k4 * 4) * 4,
                  Bg + (size_t)r * K + k0 + k4 * 4);
        }
        asm volatile("cp.async.commit_group;");
    };
    // ---- A tile: either cp.async (same group as B) or LDG-staged ----
    auto loadA_async = [&](int t) {
        const int s = t % MG_STAGES;
        const int k0 = t * 32;
        const uint32_t abase = sb + (uint32_t)(s * MG_STAGE_FLOATS) * 4;
#pragma unroll
        for (int it = 0; it < 4; it++) {
            int r = it * 32 + row;
            cpa16(abase + (uint32_t)(r * MG_STRIDE + k4 * 4) * 4,
                  Ag + (size_t)r * K + k0 + k4 * 4);
        }
    };
    float4 aStage[4];
    float4 rsStage;
    auto ldgA = [&](int t) {
        const int k0 = t * 32;
#pragma unroll
        for (int it = 0; it < 4; it++) {
            int r = it * 32 + row;
            aStage[it] = *reinterpret_cast<const float4*>(Ag + (size_t)r * K + k0 + k4 * 4);
        }
        rsStage = *reinterpret_cast<const float4*>(irs + k0 + k4 * 4);
    };
    auto stsA = [&](int t) {
        const int s = t % MG_STAGES;
        float* abase = sm + s * MG_STAGE_FLOATS;
#pragma unroll
        for (int it = 0; it < 4; it++) {
            int r = it * 32 + row;
            float4 vv = aStage[it];
            vv.x = rntf32(vv.x * rsStage.x);
            vv.y = rntf32(vv.y * rsStage.y);
            vv.z = rntf32(vv.z * rsStage.z);
            vv.w = rntf32(vv.w * rsStage.w);
            *reinterpret_cast<float4*>(abase + r * MG_STRIDE + k4 * 4) = vv;
        }
    };

    uint32_t af[2][4][4], bf[2][4][2];
    auto frag_load = [&](const float* Ab, const float* Bb, int k0, int slot) {
#pragma unroll
        for (int mf = 0; mf < 4; mf++) {
            int m = wm * 64 + mf * 16 + g;
            af[slot][mf][0] = __float_as_uint(Ab[m * MG_STRIDE + k0]);
            af[slot][mf][1] = __float_as_uint(Ab[(m + 8) * MG_STRIDE + k0]);
            af[slot][mf][2] = __float_as_uint(Ab[m * MG_STRIDE + k0 + 4]);
            af[slot][mf][3] = __float_as_uint(Ab[(m + 8) * MG_STRIDE + k0 + 4]);
        }
#pragma unroll
        for (int nf = 0; nf < 4; nf++) {
            int n = wn * 32 + nf * 8 + g;
            bf[slot][nf][0] = __float_as_uint(Bb[n * MG_STRIDE + k0]);
            bf[slot][nf][1] = __float_as_uint(Bb[n * MG_STRIDE + k0 + 4]);
        }
    };

    const int NT = K / 32;

    // ---- prologue: tiles 0,1 in flight ----
    if (SCALE_A) {
        ldgA(0); stsA(0); loadB(0);
        ldgA(1); stsA(1); loadB(1);
    } else {
        loadA_async(0); loadB(0);
        loadA_async(1); loadB(1);
    }
    asm volatile("cp.async.wait_group 1;");
    __syncthreads();
    frag_load(sm, sm + MG_TSZ, tg, 0);

    for (int t = 0; t < NT; t++) {
        const int s = t % MG_STAGES;
        const float* Ab = sm + s * MG_STAGE_FLOATS;
        const float* Bb = Ab + MG_TSZ;

#pragma unroll
        for (int ks = 0; ks < 4; ks++) {
            const int cur = ks & 1;
            const int nxt = cur ^ 1;

            if (SCALE_A && ks == 0 && t + 2 < NT)
                ldgA(t + 2);   // long-latency LDG issued 3 k-steps early

            if (ks < 3) {
                frag_load(Ab, Bb, (ks + 1) * 8 + tg, nxt);
            } else if (t + 1 < NT) {
                if (t + 2 < NT) {
                    if (SCALE_A) { stsA(t + 2); loadB(t + 2); }
                    else         { loadA_async(t + 2); loadB(t + 2); }
                    asm volatile("cp.async.wait_group 1;");
                } else {
                    asm volatile("cp.async.wait_group 0;");
                }
                __syncthreads();
                const float* An = sm + ((t + 1) % MG_STAGES) * MG_STAGE_FLOATS;
                frag_load(An, An + MG_TSZ, tg, nxt);
            }

#pragma unroll
            for (int mf = 0; mf < 4; mf++)
#pragma unroll
                for (int nf = 0; nf < 4; nf++)
                    mma_tf32(acc[mf][nf],
                             af[cur][mf][0], af[cur][mf][1],
                             af[cur][mf][2], af[cur][mf][3],
                             bf[cur][nf][0], bf[cur][nf][1]);
        }
    }

    float* Cb = C + bz * sC;
#pragma unroll
    for (int mf = 0; mf < 4; mf++) {
        const int r0 = bm + wm * 64 + mf * 16 + g;
        const int r1 = r0 + 8;
#pragma unroll
        for (int nf = 0; nf < 4; nf++) {
            const int c = bn + wn * 32 + nf * 8 + tg * 2;
            *reinterpret_cast<float2*>(&Cb[(size_t)r0 * ldc + c]) =
                make_float2(acc[mf][nf][0], acc[mf][nf][1]);
            *reinterpret_cast<float2*>(&Cb[(size_t)r1 * ldc + c]) =
                make_float2(acc[mf][nf][2], acc[mf][nf][3]);
        }
    }
}

// ============================================================================
// fp32 split-tile SGEMM.
//   EXP:  epilogue applies rntf32(__expf(.)) (P must be tf32-exact)
//   RSUM: epilogue also emits per-block column sums into rsp
// ============================================================================
template <int BM, int BN, int BK, int TM, int TN, bool AT, bool EXP, bool RSUM>
__global__ void __launch_bounds__((BM / TM) * (BN / TN))
sgemm_tpl(const float* __restrict__ A, const float* __restrict__ B,
          float* __restrict__ C, int M, int N, int K,
          long long sA, long long sB, long long sC,
          float* __restrict__ rsp)
{
    constexpr int THREADS = (BM / TM) * (BN / TN);
    constexpr int PAD = 4;
    __shared__ float As[BK][BM + PAD];
    __shared__ float Bs[BK][BN];
    __shared__ float red[RSUM ? (16 * BN) : 1];

    const long long bz = blockIdx.z;
    A += bz * sA; B += bz * sB; C += bz * sC;

    const int bm = blockIdx.y * BM;
    const int bn = blockIdx.x * BN;
    const int tid = threadIdx.x;

    constexpr int RX = BN / TN;
    const int tx = tid % RX;
    const int ty = tid / RX;
    const int tn0 = tx * (TN / 2);
    const int tm0 = ty * (TM / 2);

    float acc[TM][TN];
#pragma unroll
    for (int i = 0; i < TM; i++)
#pragma unroll
        for (int j = 0; j < TN; j++) acc[i][j] = 0.f;

    for (int k0 = 0; k0 < K; k0 += BK) {
        if (AT) {
            constexpr int NV = BM * BK / 4;
#pragma unroll
            for (int r = 0; r < NV / THREADS; r++) {
                int i = r * THREADS + tid;
                int kk = i / (BM / 4);
                int mv = i % (BM / 4);
                float4 v = *reinterpret_cast<const float4*>(
                    A + (long long)(k0 + kk) * M + bm + mv * 4);
                As[kk][mv * 4 + 0] = v.x; As[kk][mv * 4 + 1] = v.y;
                As[kk][mv * 4 + 2] = v.z; As[kk][mv * 4 + 3] = v.w;
            }
        } else {
            constexpr int NE = BM * BK;
#pragma unroll
            for (int r = 0; r < NE / THREADS; r++) {
                int i = r * THREADS + tid;
                int mm = i / BK;
                int kk = i % BK;
                As[kk][mm] = A[(long long)(bm + mm) * K + k0 + kk];
            }
        }
        constexpr int NBV = BK * BN / 4;
#pragma unroll
        for (int r = 0; r < NBV / THREADS; r++) {
            int i = r * THREADS + tid;
            int kk = i / (BN / 4);
            int nv = i % (BN / 4);
            float4 v = *reinterpret_cast<const float4*>(
                B + (long long)(k0 + kk) * N + bn + nv * 4);
            *reinterpret_cast<float4*>(&Bs[kk][nv * 4]) = v;
        }
        __syncthreads();

#pragma unroll
        for (int kk = 0; kk < BK; kk++) {
            float ar[TM], br[TN];
#pragma unroll
            for (int i = 0; i < TM / 2; i++) {
                ar[i]          = As[kk][tm0 + i];
                ar[TM / 2 + i] = As[kk][BM / 2 + tm0 + i];
            }
#pragma unroll
            for (int j = 0; j < TN / 2; j++) {
                br[j]          = Bs[kk][tn0 + j];
                br[TN / 2 + j] = Bs[kk][BN / 2 + tn0 + j];
            }
#pragma unroll
            for (int i = 0; i < TM; i++)
#pragma unroll
                for (int j = 0; j < TN; j++)
                    acc[i][j] = fmaf(ar[i], br[j], acc[i][j]);
        }
        __syncthreads();
    }

    float cs[TN];
    if (RSUM) {
#pragma unroll
        for (int j = 0; j < TN; j++) cs[j] = 0.f;
    }
#pragma unroll
    for (int i = 0; i < TM; i++) {
        int row = bm + ((i < TM / 2) ? (tm0 + i) : (BM / 2 + tm0 + i - TM / 2));
        float* Cr = C + (long long)row * N + bn;
        float4 v0, v1;
        {
            float e0 = acc[i][0], e1 = acc[i][1], e2 = acc[i][2], e3 = acc[i][3];
            if (EXP) {
                e0 = rntf32(__expf(e0)); e1 = rntf32(__expf(e1));
                e2 = rntf32(__expf(e2)); e3 = rntf32(__expf(e3));
            }
            if (RSUM) { cs[0] += e0; cs[1] += e1; cs[2] += e2; cs[3] += e3; }
            v0 = make_float4(e0, e1, e2, e3);
        }
        {
            float e0 = acc[i][4], e1 = acc[i][5], e2 = acc[i][6], e3 = acc[i][7];
            if (EXP) {
                e0 = rntf32(__expf(e0)); e1 = rntf32(__expf(e1));
                e2 = rntf32(__expf(e2)); e3 = rntf32(__expf(e3));
            }
            if (RSUM) { cs[4] += e0; cs[5] += e1; cs[6] += e2; cs[7] += e3; }
            v1 = make_float4(e0, e1, e2, e3);
        }
        *reinterpret_cast<float4*>(&Cr[tn0])          = v0;
        *reinterpret_cast<float4*>(&Cr[BN / 2 + tn0]) = v1;
    }

    if (RSUM) {
        *reinterpret_cast<float4*>(&red[ty * BN + tn0]) =
            make_float4(cs[0], cs[1], cs[2], cs[3]);
        *reinterpret_cast<float4*>(&red[ty * BN + BN / 2 + tn0]) =
            make_float4(cs[4], cs[5], cs[6], cs[7]);
        __syncthreads();
        if (tid < BN) {
            float s = 0.f;
#pragma unroll
            for (int t = 0; t < 16; t++) s += red[t * BN + tid];
            rsp[((size_t)bz * 32 + blockIdx.y) * NN + bn + tid] = s;
        }
    }
}

// ============================================================================
// x[b][c][n] -> xT[b][n][c], rounded to tf32
// ============================================================================
__global__ void transpose_k(const float* __restrict__ x, float* __restrict__ xT)
{
    __shared__ float t[32][33];
    const size_t base = (size_t)blockIdx.z * CC * NN;
    const int c0 = blockIdx.y * 32;
    const int n0 = blockIdx.x * 32;
    const float* xi = x + base;
    float* xo = xT + base;
#pragma unroll
    for (int i = threadIdx.y; i < 32; i += 8)
        t[i][threadIdx.x] = xi[(size_t)(c0 + i) * NN + n0 + threadIdx.x];
    __syncthreads();
#pragma unroll
    for (int i = threadIdx.y; i < 32; i += 8)
        xo[(size_t)(n0 + i) * CC + c0 + threadIdx.x] = rntf32(t[threadIdx.x][i]);
}

// Wv -> g_Wv rounded to tf32
__global__ void roundw_k(const float* __restrict__ W, float* __restrict__ Wo)
{
    int i = blockIdx.x * 256 + threadIdx.x;
    Wo[i] = rntf32(W[i]);
}

// Concat [Wq; Wk] -> g_Wqk
__global__ void concatw_k(const float* __restrict__ Wq, const float* __restrict__ Wk,
                          float* __restrict__ Wo)
{
    int i = blockIdx.x * 256 + threadIdx.x;
    Wo[i] = (i < DD * CC) ? Wq[i] : Wk[i - DD * CC];
}

// Final reduction: irs[b][m] = 1 / sum_j rsp[b][j][m]
__global__ void colsum_final(const float* __restrict__ rsp, float* __restrict__ irs)
{
    const int m = blockIdx.x * 256 + threadIdx.x;
    const int b = blockIdx.y;
    float s = 0.f;
#pragma unroll
    for (int j = 0; j < 32; j++) s += rsp[((size_t)b * 32 + j) * NN + m];
    irs[b * NN + m] = 1.0f / s;
}

// ============================================================================
extern "C" void kernel_launch(void* const* d_in, const int* in_sizes, int n_in,
                              void* d_out, int out_size)
{
    const float* x = nullptr;
    const float* Wq = nullptr;
    const float* Wk = nullptr;
    const float* Wv = nullptr;
    for (int i = 0; i < n_in; i++) {
        int sz = in_sizes[i];
        const float* p = (const float*)d_in[i];
        if (sz == BB * CC * NN)      x = p;
        else if (sz == CC * CC)      Wv = p;
        else if (sz == DD * CC) { if (!Wq) Wq = p; else Wk = p; }
    }
    float* out = (float*)d_out;

    float *qk, *v, *xT, *P, *Wvr, *Wqk, *rsp, *irs;
    cudaGetSymbolAddress((void**)&qk,  g_qk);
    cudaGetSymbolAddress((void**)&v,   g_v);
    cudaGetSymbolAddress((void**)&xT,  g_xT);
    cudaGetSymbolAddress((void**)&P,   g_P);
    cudaGetSymbolAddress((void**)&Wvr, g_Wv);
    cudaGetSymbolAddress((void**)&Wqk, g_Wqk);
    cudaGetSymbolAddress((void**)&rsp, g_rsp);
    cudaGetSymbolAddress((void**)&irs, g_irs);

    cudaFuncSetAttribute(mma_gemm<false>, cudaFuncAttributeMaxDynamicSharedMemorySize,
                         MG_SMEM_BYTES);
    cudaFuncSetAttribute(mma_gemm<true>, cudaFuncAttributeMaxDynamicSharedMemorySize,
                         MG_SMEM_BYTES);

    const long long sX  = (long long)CC * NN;
    const long long sQK = (long long)2 * DD * NN;
    const long long sP  = (long long)NN * NN;

    // 0) weight prep
    roundw_k<<<(CC * CC) / 256, 256>>>(Wv, Wvr);
    concatw_k<<<(2 * DD * CC) / 256, 256>>>(Wq, Wk, Wqk);

    // 1) xT = transpose(x) per batch, tf32-rounded
    transpose_k<<<dim3(NN / 32, CC / 32, BB), dim3(32, 8)>>>(x, xT);

    // 2) v[c][m] = Wv @ xT   (tf32 mma.sync; v raw fp32, scaled+rounded later)
    mma_gemm<false><<<dim3(NN / 128, CC / 128, BB), 256, MG_SMEM_BYTES>>>(
        Wvr, xT, nullptr, v, CC, 0, sX, sX, NN);

    // 3) qk = [Wq; Wk] @ x   (fp32, one pass over x)
    sgemm_tpl<64, 128, 8, 4, 8, false, false, false>
        <<<dim3(NN / 128, 1, BB), 256>>>(Wqk, x, qk, 2 * DD, NN, CC, 0, sX, sQK, nullptr);

    // 4) P'[n][m] = exp(k^T q)  (fp32 AT; tf32-rounded; fused column partials)
    sgemm_tpl<128, 128, 8, 8, 8, true, true, true>
        <<<dim3(NN / 128, NN / 128, BB), 256>>>(
            qk + (size_t)DD * NN, qk, P, NN, NN, DD, sQK, sQK, sP, rsp);

    // 5) finish rowsums -> reciprocal
    colsum_final<<<dim3(NN / 256, BB), 256>>>(rsp, irs);

    // 6) out[c][n] = sum_m (v[c][m]*irs[m]) * P'[n][m]   (tf32 mma.sync,
    //    scaling + tf32-rounding fused into the A-tile smem load)
    mma_gemm<true><<<dim3(NN / 128, CC / 128, BB), 256, MG_SMEM_BYTES>>>(
        v, P, irs, out, NN, sX, sP, sX, NN);
}

// round 14
// speedup vs baseline: 1.4221x; 1.4221x over previous
#include <cuda_runtime.h>
#include <cuda_fp16.h>
#include <cstdint>
#include <math.h>

// Problem constants
#define BB 8
#define CC 512
#define NN 4096   // H*W
#define DD 32     // C / R

// Scratch (allocation-free rule: __device__ globals)
__device__ float  g_qk[BB * 2 * DD * NN];              // [b][64][n]: rows 0-31=q, 32-63=k
__device__ float  g_v [(size_t)BB * CC * NN];          // v[b][c][m]  raw fp32 (64 MB)
__device__ __half g_v16[(size_t)BB * CC * NN];         // v fp16 (32 MB)
__device__ float  g_xT[(size_t)BB * CC * NN];          // xT[b][n][c] tf32-rounded (64 MB)
__device__ __half g_P16[(size_t)BB * NN * NN];         // P̃[b][n][m] = fp16(exp·irs) (256 MB)
__device__ float  g_Wv[CC * CC];                       // Wv tf32-rounded
__device__ float  g_Wqk[2 * DD * CC];                  // concat [Wq; Wk]
__device__ float  g_rsp[BB * 32 * NN];                 // partial column sums
__device__ float  g_irs[BB * NN];                      // 1 / rowsum[b][m]

// ============================================================================
// helpers
// ============================================================================
__device__ __forceinline__ uint32_t smem_u32(const void* p) {
    uint32_t a;
    asm("{ .reg .u64 t; cvta.to.shared.u64 t, %1; cvt.u32.u64 %0, t; }"
        : "=r"(a) : "l"(p));
    return a;
}
__device__ __forceinline__ void cpa16(uint32_t dst, const void* src) {
    asm volatile("cp.async.cg.shared.global [%0], [%1], 16;"
                 :: "r"(dst), "l"(src));
}
__device__ __forceinline__ float rntf32(float f) {
    uint32_t u;
    asm("cvt.rna.tf32.f32 %0, %1;" : "=r"(u) : "f"(f));
    return __uint_as_float(u);
}
__device__ __forceinline__ void mma_tf32(float c[4],
                                         uint32_t a0, uint32_t a1, uint32_t a2, uint32_t a3,
                                         uint32_t b0, uint32_t b1) {
    asm volatile(
        "mma.sync.aligned.m16n8k8.row.col.f32.tf32.tf32.f32 "
        "{%0,%1,%2,%3}, {%4,%5,%6,%7}, {%8,%9}, {%0,%1,%2,%3};"
        : "+f"(c[0]), "+f"(c[1]), "+f"(c[2]), "+f"(c[3])
        : "r"(a0), "r"(a1), "r"(a2), "r"(a3), "r"(b0), "r"(b1));
}
__device__ __forceinline__ void mma_f16(float c[4],
                                        uint32_t a0, uint32_t a1, uint32_t a2, uint32_t a3,
                                        uint32_t b0, uint32_t b1) {
    asm volatile(
        "mma.sync.aligned.m16n8k16.row.col.f32.f16.f16.f32 "
        "{%0,%1,%2,%3}, {%4,%5,%6,%7}, {%8,%9}, {%0,%1,%2,%3};"
        : "+f"(c[0]), "+f"(c[1]), "+f"(c[2]), "+f"(c[3])
        : "r"(a0), "r"(a1), "r"(a2), "r"(a3), "r"(b0), "r"(b1));
}

// ============================================================================
// tf32 mma.sync GEMM (v-proj): C[m][n] = sum_k A[m][k] * B[n][k]
// Block tile 128x128x32; 8 warps 64x32; 3-stage + cross-tile frag ping-pong.
// Inputs pre-rounded to tf32.
// ============================================================================
#define MG_STRIDE 36
#define MG_TSZ (128 * MG_STRIDE)
#define MG_STAGE_FLOATS (2 * MG_TSZ)
#define MG_STAGES 3
#define MG_SMEM_BYTES (MG_STAGES * MG_STAGE_FLOATS * 4)   // 110592

__global__ void __launch_bounds__(256)
mma_gemm(const float* __restrict__ A, const float* __restrict__ B,
         float* __restrict__ C, int K,
         long long sA, long long sB, long long sC, int ldc)
{
    extern __shared__ float sm[];
    const uint32_t sb = smem_u32(sm);

    const int tid = threadIdx.x;
    const int lane = tid & 31;
    const int wid = tid >> 5;
    const int g = lane >> 2;
    const int tg = lane & 3;
    const int wm = wid & 1;
    const int wn = wid >> 1;

    const long long bz = blockIdx.z;
    const int bm = blockIdx.y * 128;
    const int bn = blockIdx.x * 128;
    const float* Ag = A + bz * sA + (size_t)bm * K;
    const float* Bg = B + bz * sB + (size_t)bn * K;

    float acc[4][4][4];
#pragma unroll
    for (int mf = 0; mf < 4; mf++)
#pragma unroll
        for (int nf = 0; nf < 4; nf++)
#pragma unroll
            for (int i = 0; i < 4; i++) acc[mf][nf][i] = 0.f;

    const int row = tid >> 3;
    const int k4  = tid & 7;

    auto load_tile = [&](int t) {
        const int s = t % MG_STAGES;
        const int k0 = t * 32;
        const uint32_t abase = sb + (uint32_t)(s * MG_STAGE_FLOATS) * 4;
        const uint32_t bbase = abase + (uint32_t)MG_TSZ * 4;
#pragma unroll
        for (int it = 0; it < 4; it++) {
            int r = it * 32 + row;
            cpa16(abase + (uint32_t)(r * MG_STRIDE + k4 * 4) * 4,
                  Ag + (size_t)r * K + k0 + k4 * 4);
        }
#pragma unroll
        for (int it = 0; it < 4; it++) {
            int r = it * 32 + row;
            cpa16(bbase + (uint32_t)(r * MG_STRIDE + k4 * 4) * 4,
                  Bg + (size_t)r * K + k0 + k4 * 4);
        }
        asm volatile("cp.async.commit_group;");
    };

    uint32_t af[2][4][4], bf[2][4][2];
    auto frag_load = [&](const float* Ab, const float* Bb, int k0, int slot) {
#pragma unroll
        for (int mf = 0; mf < 4; mf++) {
            int m = wm * 64 + mf * 16 + g;
            af[slot][mf][0] = __float_as_uint(Ab[m * MG_STRIDE + k0]);
            af[slot][mf][1] = __float_as_uint(Ab[(m + 8) * MG_STRIDE + k0]);
            af[slot][mf][2] = __float_as_uint(Ab[m * MG_STRIDE + k0 + 4]);
            af[slot][mf][3] = __float_as_uint(Ab[(m + 8) * MG_STRIDE + k0 + 4]);
        }
#pragma unroll
        for (int nf = 0; nf < 4; nf++) {
            int n = wn * 32 + nf * 8 + g;
            bf[slot][nf][0] = __float_as_uint(Bb[n * MG_STRIDE + k0]);
            bf[slot][nf][1] = __float_as_uint(Bb[n * MG_STRIDE + k0 + 4]);
        }
    };

    const int NT = K / 32;

    load_tile(0);
    load_tile(1);
    asm volatile("cp.async.wait_group 1;");
    __syncthreads();
    frag_load(sm, sm + MG_TSZ, tg, 0);

    for (int t = 0; t < NT; t++) {
        const int s = t % MG_STAGES;
        const float* Ab = sm + s * MG_STAGE_FLOATS;
        const float* Bb = Ab + MG_TSZ;

#pragma unroll
        for (int ks = 0; ks < 4; ks++) {
            const int cur = ks & 1;
            const int nxt = cur ^ 1;

            if (ks < 3) {
                frag_load(Ab, Bb, (ks + 1) * 8 + tg, nxt);
            } else if (t + 1 < NT) {
                if (t + 2 < NT) {
                    load_tile(t + 2);
                    asm volatile("cp.async.wait_group 1;");
                } else {
                    asm volatile("cp.async.wait_group 0;");
                }
                __syncthreads();
                const float* An = sm + ((t + 1) % MG_STAGES) * MG_STAGE_FLOATS;
                frag_load(An, An + MG_TSZ, tg, nxt);
            }

#pragma unroll
            for (int mf = 0; mf < 4; mf++)
#pragma unroll
                for (int nf = 0; nf < 4; nf++)
                    mma_tf32(acc[mf][nf],
                             af[cur][mf][0], af[cur][mf][1],
                             af[cur][mf][2], af[cur][mf][3],
                             bf[cur][nf][0], bf[cur][nf][1]);
        }
    }

    float* Cb = C + bz * sC;
#pragma unroll
    for (int mf = 0; mf < 4; mf++) {
        const int r0 = bm + wm * 64 + mf * 16 + g;
        const int r1 = r0 + 8;
#pragma unroll
        for (int nf = 0; nf < 4; nf++) {
            const int c = bn + wn * 32 + nf * 8 + tg * 2;
            *reinterpret_cast<float2*>(&Cb[(size_t)r0 * ldc + c]) =
                make_float2(acc[mf][nf][0], acc[mf][nf][1]);
            *reinterpret_cast<float2*>(&Cb[(size_t)r1 * ldc + c]) =
                make_float2(acc[mf][nf][2], acc[mf][nf][3]);
        }
    }
}

// ============================================================================
// fp16 mma.sync GEMM (out-GEMM): C[m][n] = sum_k A[m][k] * B[n][k], fp32 acc.
// Block tile 128x128x64 (4 k16 steps); 8 warps 64x32; 3-stage cp.async.
// ============================================================================
#define HG_ST 72                                   // halfs per smem row
#define HG_TSZ (128 * HG_ST)                       // halfs per operand tile
#define HG_STAGE_HALFS (2 * HG_TSZ)
#define HG_STAGES 3
#define HG_SMEM_BYTES (HG_STAGES * HG_STAGE_HALFS * 2)   // 110592

__global__ void __launch_bounds__(256)
hgemm(const __half* __restrict__ A, const __half* __restrict__ B,
      float* __restrict__ C, int K,
      long long sA, long long sB, long long sC, int ldc)
{
    extern __shared__ __half hsm[];
    const uint32_t sb = smem_u32(hsm);

    const int tid = threadIdx.x;
    const int lane = tid & 31;
    const int wid = tid >> 5;
    const int g = lane >> 2;
    const int tg = lane & 3;
    const int wm = wid & 1;
    const int wn = wid >> 1;

    const long long bz = blockIdx.z;
    const int bm = blockIdx.y * 128;
    const int bn = blockIdx.x * 128;
    const __half* Ag = A + bz * sA + (size_t)bm * K;
    const __half* Bg = B + bz * sB + (size_t)bn * K;

    float acc[4][4][4];
#pragma unroll
    for (int mf = 0; mf < 4; mf++)
#pragma unroll
        for (int nf = 0; nf < 4; nf++)
#pragma unroll
            for (int i = 0; i < 4; i++) acc[mf][nf][i] = 0.f;

    const int row = tid >> 3;      // 0..31
    const int c8  = tid & 7;       // 16B chunk (8 halfs)

    auto load_tile = [&](int t) {
        const int s = t % HG_STAGES;
        const int k0 = t * 64;
        const uint32_t abase = sb + (uint32_t)(s * HG_STAGE_HALFS) * 2;
        const uint32_t bbase = abase + (uint32_t)HG_TSZ * 2;
#pragma unroll
        for (int it = 0; it < 4; it++) {
            int r = it * 32 + row;
            cpa16(abase + (uint32_t)(r * HG_ST + c8 * 8) * 2,
                  Ag + (size_t)r * K + k0 + c8 * 8);
        }
#pragma unroll
        for (int it = 0; it < 4; it++) {
            int r = it * 32 + row;
            cpa16(bbase + (uint32_t)(r * HG_ST + c8 * 8) * 2,
                  Bg + (size_t)r * K + k0 + c8 * 8);
        }
        asm volatile("cp.async.commit_group;");
    };

    const int NT = K / 64;
    load_tile(0);
    load_tile(1);
    asm volatile("cp.async.wait_group 1;");
    __syncthreads();

    for (int t = 0; t < NT; t++) {
        const int s = t % HG_STAGES;
        const __half* Ab = hsm + s * HG_STAGE_HALFS;
        const __half* Bb = Ab + HG_TSZ;

#pragma unroll
        for (int ks = 0; ks < 4; ks++) {
            const int k0 = ks * 16 + 2 * tg;
            uint32_t a[4][4], b[4][2];
#pragma unroll
            for (int mf = 0; mf < 4; mf++) {
                int m = wm * 64 + mf * 16 + g;
                a[mf][0] = *reinterpret_cast<const uint32_t*>(Ab + m * HG_ST + k0);
                a[mf][1] = *reinterpret_cast<const uint32_t*>(Ab + (m + 8) * HG_ST + k0);
                a[mf][2] = *reinterpret_cast<const uint32_t*>(Ab + m * HG_ST + k0 + 8);
                a[mf][3] = *reinterpret_cast<const uint32_t*>(Ab + (m + 8) * HG_ST + k0 + 8);
            }
#pragma unroll
            for (int nf = 0; nf < 4; nf++) {
                int n = wn * 32 + nf * 8 + g;
                b[nf][0] = *reinterpret_cast<const uint32_t*>(Bb + n * HG_ST + k0);
                b[nf][1] = *reinterpret_cast<const uint32_t*>(Bb + n * HG_ST + k0 + 8);
            }
#pragma unroll
            for (int mf = 0; mf < 4; mf++)
#pragma unroll
                for (int nf = 0; nf < 4; nf++)
                    mma_f16(acc[mf][nf],
                            a[mf][0], a[mf][1], a[mf][2], a[mf][3],
                            b[nf][0], b[nf][1]);
        }

        if (t + 1 < NT) {
            if (t + 2 < NT) {
                load_tile(t + 2);
                asm volatile("cp.async.wait_group 1;");
            } else {
                asm volatile("cp.async.wait_group 0;");
            }
            __syncthreads();
        }
    }

    float* Cb = C + bz * sC;
#pragma unroll
    for (int mf = 0; mf < 4; mf++) {
        const int r0 = bm + wm * 64 + mf * 16 + g;
        const int r1 = r0 + 8;
#pragma unroll
        for (int nf = 0; nf < 4; nf++) {
            const int c = bn + wn * 32 + nf * 8 + tg * 2;
            *reinterpret_cast<float2*>(&Cb[(size_t)r0 * ldc + c]) =
                make_float2(acc[mf][nf][0], acc[mf][nf][1]);
            *reinterpret_cast<float2*>(&Cb[(size_t)r1 * ldc + c]) =
                make_float2(acc[mf][nf][2], acc[mf][nf][3]);
        }
    }
}

// ============================================================================
// fp32 split-tile SGEMM.
//   EMODE 0: plain fp32 store (qk projection)
//   EMODE 1: exp + per-block column sums into rsp; NO C store (logits pass 1)
//   EMODE 2: store fp16(exp * irs[col]) into Ch (logits pass 2)
// ============================================================================
template <int BM, int BN, int BK, int TM, int TN, bool AT, int EMODE>
__global__ void __launch_bounds__((BM / TM) * (BN / TN))
sgemm_tpl(const float* __restrict__ A, const float* __restrict__ B,
          float* __restrict__ C, __half* __restrict__ Ch,
          int M, int N, int K,
          long long sA, long long sB, long long sC,
          float* __restrict__ rsp, const float* __restrict__ irs)
{
    constexpr int THREADS = (BM / TM) * (BN / TN);
    constexpr int PAD = 4;
    __shared__ float As[BK][BM + PAD];
    __shared__ float Bs[BK][BN];
    __shared__ float red[(EMODE == 1) ? (16 * BN) : 1];

    const long long bz = blockIdx.z;
    A += bz * sA; B += bz * sB;

    const int bm = blockIdx.y * BM;
    const int bn = blockIdx.x * BN;
    const int tid = threadIdx.x;

    constexpr int RX = BN / TN;
    const int tx = tid % RX;
    const int ty = tid / RX;
    const int tn0 = tx * (TN / 2);
    const int tm0 = ty * (TM / 2);

    float acc[TM][TN];
#pragma unroll
    for (int i = 0; i < TM; i++)
#pragma unroll
        for (int j = 0; j < TN; j++) acc[i][j] = 0.f;

    for (int k0 = 0; k0 < K; k0 += BK) {
        if (AT) {
            constexpr int NV = BM * BK / 4;
#pragma unroll
            for (int r = 0; r < NV / THREADS; r++) {
                int i = r * THREADS + tid;
                int kk = i / (BM / 4);
                int mv = i % (BM / 4);
                float4 v = *reinterpret_cast<const float4*>(
                    A + (long long)(k0 + kk) * M + bm + mv * 4);
                As[kk][mv * 4 + 0] = v.x; As[kk][mv * 4 + 1] = v.y;
                As[kk][mv * 4 + 2] = v.z; As[kk][mv * 4 + 3] = v.w;
            }
        } else {
            constexpr int NE = BM * BK;
#pragma unroll
            for (int r = 0; r < NE / THREADS; r++) {
                int i = r * THREADS + tid;
                int mm = i / BK;
                int kk = i % BK;
                As[kk][mm] = A[(long long)(bm + mm) * K + k0 + kk];
            }
        }
        constexpr int NBV = BK * BN / 4;
#pragma unroll
        for (int r = 0; r < NBV / THREADS; r++) {
            int i = r * THREADS + tid;
            int kk = i / (BN / 4);
            int nv = i % (BN / 4);
            float4 v = *reinterpret_cast<const float4*>(
                B + (long long)(k0 + kk) * N + bn + nv * 4);
            *reinterpret_cast<float4*>(&Bs[kk][nv * 4]) = v;
        }
        __syncthreads();

#pragma unroll
        for (int kk = 0; kk < BK; kk++) {
            float ar[TM], br[TN];
#pragma unroll
            for (int i = 0; i < TM / 2; i++) {
                ar[i]          = As[kk][tm0 + i];
                ar[TM / 2 + i] = As[kk][BM / 2 + tm0 + i];
            }
#pragma unroll
            for (int j = 0; j < TN / 2; j++) {
                br[j]          = Bs[kk][tn0 + j];
                br[TN / 2 + j] = Bs[kk][BN / 2 + tn0 + j];
            }
#pragma unroll
            for (int i = 0; i < TM; i++)
#pragma unroll
                for (int j = 0; j < TN; j++)
                    acc[i][j] = fmaf(ar[i], br[j], acc[i][j]);
        }
        __syncthreads();
    }

    // ---- epilogue ----
    if (EMODE == 0) {
        float* Cb = C + bz * sC;
#pragma unroll
        for (int i = 0; i < TM; i++) {
            int rowg = bm + ((i < TM / 2) ? (tm0 + i) : (BM / 2 + tm0 + i - TM / 2));
            float* Cr = Cb + (long long)rowg * N + bn;
            *reinterpret_cast<float4*>(&Cr[tn0]) =
                make_float4(acc[i][0], acc[i][1], acc[i][2], acc[i][3]);
            *reinterpret_cast<float4*>(&Cr[BN / 2 + tn0]) =
                make_float4(acc[i][4], acc[i][5], acc[i][6], acc[i][7]);
        }
    }
    if (EMODE == 1) {
        float cs[TN];
#pragma unroll
        for (int j = 0; j < TN; j++) cs[j] = 0.f;
#pragma unroll
        for (int i = 0; i < TM; i++) {
#pragma unroll
            for (int j = 0; j < TN; j++) cs[j] += __expf(acc[i][j]);
        }
        *reinterpret_cast<float4*>(&red[ty * BN + tn0]) =
            make_float4(cs[0], cs[1], cs[2], cs[3]);
        *reinterpret_cast<float4*>(&red[ty * BN + BN / 2 + tn0]) =
            make_float4(cs[4], cs[5], cs[6], cs[7]);
        __syncthreads();
        if (tid < BN) {
            float s = 0.f;
#pragma unroll
            for (int t = 0; t < 16; t++) s += red[t * BN + tid];
            rsp[((size_t)bz * 32 + blockIdx.y) * NN + bn + tid] = s;
        }
    }
    if (EMODE == 2) {
        const float* irs_b = irs + bz * NN;
        float iv[TN];
#pragma unroll
        for (int j = 0; j < TN; j++) {
            int col = bn + ((j < TN / 2) ? (tn0 + j) : (BN / 2 + tn0 + j - TN / 2));
            iv[j] = irs_b[col];
        }
        __half* Cb = Ch + bz * sC;
#pragma unroll
        for (int i = 0; i < TM; i++) {
            int rowg = bm + ((i < TM / 2) ? (tm0 + i) : (BM / 2 + tm0 + i - TM / 2));
            __half* Cr = Cb + (long long)rowg * N + bn;
            uint32_t p[4];
#pragma unroll
            for (int h = 0; h < 4; h++) {
                int j0 = h * 2, j1 = h * 2 + 1;
                __half h0 = __float2half_rn(__expf(acc[i][j0]) * iv[j0]);
                __half h1 = __float2half_rn(__expf(acc[i][j1]) * iv[j1]);
                p[h] = (uint32_t)__half_as_ushort(h0) |
                       ((uint32_t)__half_as_ushort(h1) << 16);
            }
            *reinterpret_cast<uint2*>(&Cr[tn0]) = make_uint2(p[0], p[1]);
            *reinterpret_cast<uint2*>(&Cr[BN / 2 + tn0]) = make_uint2(p[2], p[3]);
        }
    }
}

// ============================================================================
// x[b][c][n] -> xT[b][n][c], rounded to tf32
// ============================================================================
__global__ void transpose_k(const float* __restrict__ x, float* __restrict__ xT)
{
    __shared__ float t[32][33];
    const size_t base = (size_t)blockIdx.z * CC * NN;
    const int c0 = blockIdx.y * 32;
    const int n0 = blockIdx.x * 32;
    const float* xi = x + base;
    float* xo = xT + base;
#pragma unroll
    for (int i = threadIdx.y; i < 32; i += 8)
        t[i][threadIdx.x] = xi[(size_t)(c0 + i) * NN + n0 + threadIdx.x];
    __syncthreads();
#pragma unroll
    for (int i = threadIdx.y; i < 32; i += 8)
        xo[(size_t)(n0 + i) * CC + c0 + threadIdx.x] = rntf32(t[threadIdx.x][i]);
}

// Wv -> g_Wv rounded to tf32
__global__ void roundw_k(const float* __restrict__ W, float* __restrict__ Wo)
{
    int i = blockIdx.x * 256 + threadIdx.x;
    Wo[i] = rntf32(W[i]);
}

// Concat [Wq; Wk] -> g_Wqk
__global__ void concatw_k(const float* __restrict__ Wq, const float* __restrict__ Wk,
                          float* __restrict__ Wo)
{
    int i = blockIdx.x * 256 + threadIdx.x;
    Wo[i] = (i < DD * CC) ? Wq[i] : Wk[i - DD * CC];
}

// Final reduction: irs[b][m] = 1 / sum_j rsp[b][j][m]
__global__ void colsum_final(const float* __restrict__ rsp, float* __restrict__ irs)
{
    const int m = blockIdx.x * 256 + threadIdx.x;
    const int b = blockIdx.y;
    float s = 0.f;
#pragma unroll
    for (int j = 0; j < 32; j++) s += rsp[((size_t)b * 32 + j) * NN + m];
    irs[b * NN + m] = 1.0f / s;
}

// v fp32 -> fp16 (RN)
__global__ void roundv16(const float* __restrict__ v, __half* __restrict__ v16)
{
    size_t i = ((size_t)blockIdx.x * 256 + threadIdx.x) * 4;
    float4 f = *reinterpret_cast<const float4*>(v + i);
    __half2 lo = __floats2half2_rn(f.x, f.y);
    __half2 hi = __floats2half2_rn(f.z, f.w);
    *reinterpret_cast<__half2*>(v16 + i)     = lo;
    *reinterpret_cast<__half2*>(v16 + i + 2) = hi;
}

// ============================================================================
extern "C" void kernel_launch(void* const* d_in, const int* in_sizes, int n_in,
                              void* d_out, int out_size)
{
    const float* x = nullptr;
    const float* Wq = nullptr;
    const float* Wk = nullptr;
    const float* Wv = nullptr;
    for (int i = 0; i < n_in; i++) {
        int sz = in_sizes[i];
        const float* p = (const float*)d_in[i];
        if (sz == BB * CC * NN)      x = p;
        else if (sz == CC * CC)      Wv = p;
        else if (sz == DD * CC) { if (!Wq) Wq = p; else Wk = p; }
    }
    float* out = (float*)d_out;

    float *qk, *v, *xT, *Wvr, *Wqk, *rsp, *irs;
    __half *v16, *P16;
    cudaGetSymbolAddress((void**)&qk,  g_qk);
    cudaGetSymbolAddress((void**)&v,   g_v);
    cudaGetSymbolAddress((void**)&v16, g_v16);
    cudaGetSymbolAddress((void**)&xT,  g_xT);
    cudaGetSymbolAddress((void**)&P16, g_P16);
    cudaGetSymbolAddress((void**)&Wvr, g_Wv);
    cudaGetSymbolAddress((void**)&Wqk, g_Wqk);
    cudaGetSymbolAddress((void**)&rsp, g_rsp);
    cudaGetSymbolAddress((void**)&irs, g_irs);

    cudaFuncSetAttribute(mma_gemm, cudaFuncAttributeMaxDynamicSharedMemorySize,
                         MG_SMEM_BYTES);
    cudaFuncSetAttribute(hgemm, cudaFuncAttributeMaxDynamicSharedMemorySize,
                         HG_SMEM_BYTES);

    const long long sX  = (long long)CC * NN;
    const long long sQK = (long long)2 * DD * NN;
    const long long sP  = (long long)NN * NN;

    // 0) weight prep
    roundw_k<<<(CC * CC) / 256, 256>>>(Wv, Wvr);
    concatw_k<<<(2 * DD * CC) / 256, 256>>>(Wq, Wk, Wqk);

    // 1) xT = transpose(x) per batch, tf32-rounded
    transpose_k<<<dim3(NN / 32, CC / 32, BB), dim3(32, 8)>>>(x, xT);

    // 2) v[c][m] = Wv @ xT   (tf32 mma.sync)
    mma_gemm<<<dim3(NN / 128, CC / 128, BB), 256, MG_SMEM_BYTES>>>(
        Wvr, xT, v, CC, 0, sX, sX, NN);

    // 3) qk = [Wq; Wk] @ x   (fp32, one pass over x)
    sgemm_tpl<64, 128, 8, 4, 8, false, 0>
        <<<dim3(NN / 128, 1, BB), 256>>>(Wqk, x, qk, nullptr,
                                         2 * DD, NN, CC, 0, sX, sQK, nullptr, nullptr);

    // 4a) logits pass 1: rowsums of exp(k^T q) only (no P store)
    sgemm_tpl<128, 128, 8, 8, 8, true, 1>
        <<<dim3(NN / 128, NN / 128, BB), 256>>>(
            qk + (size_t)DD * NN, qk, nullptr, nullptr,
            NN, NN, DD, sQK, sQK, 0, rsp, nullptr);

    // 4b) irs = 1/rowsum
    colsum_final<<<dim3(NN / 256, BB), 256>>>(rsp, irs);

    // 4c) logits pass 2: P16[n][m] = fp16(exp(k^T q) * irs[m])
    sgemm_tpl<128, 128, 8, 8, 8, true, 2>
        <<<dim3(NN / 128, NN / 128, BB), 256>>>(
            qk + (size_t)DD * NN, qk, nullptr, P16,
            NN, NN, DD, sQK, sQK, sP, nullptr, irs);

    // 5) v -> fp16
    roundv16<<<((size_t)BB * CC * NN) / 1024, 256>>>(v, v16);

    // 6) out[c][n] = sum_m v16[c][m] * P16[n][m]   (fp16 mma.sync, fp32 acc)
    hgemm<<<dim3(NN / 128, CC / 128, BB), 256, HG_SMEM_BYTES>>>(
        v16, P16, out, NN, sX, sP, sX, NN);
}